// round 1
// baseline (speedup 1.0000x reference)
#include <cuda_runtime.h>
#include <math.h>

#define BB 8
#define SS 2048
#define DD 512

// Scratch (device globals: allocation-free per harness rules)
__device__ __align__(16) float g_q[(size_t)BB * SS * DD];
__device__ __align__(16) float g_k[(size_t)BB * SS * DD];
__device__ __align__(16) float g_v[(size_t)BB * SS * DD];
__device__ __align__(16) float g_sc[(size_t)BB * SS * SS];

// ---------------------------------------------------------------------------
// Tiled block GEMM: computes a 128x128 tile of C = A * B(^T)
// A: row-major [M, K] with leading dim ldA
// TRANSB=true : B row-major [N, K], ldB = K  (C = A * B^T)
// TRANSB=false: B row-major [K, N], ldB = N  (C = A * B)
// 256 threads, each owns an 8x8 accumulator. BK = 16.
// ---------------------------------------------------------------------------
template <bool TRANSB>
__device__ __forceinline__ void gemm_block(const float* __restrict__ A,
                                           const float* __restrict__ Bp,
                                           int K, int ldA, int ldB,
                                           float acc[8][8]) {
    __shared__ float As[16][128];
    __shared__ float Bs[16][128];
    const int tid = threadIdx.x;
    const int m0 = blockIdx.y * 128;
    const int n0 = blockIdx.x * 128;
    const int ty = tid >> 4;   // 0..15
    const int tx = tid & 15;   // 0..15

#pragma unroll
    for (int i = 0; i < 8; i++)
#pragma unroll
        for (int j = 0; j < 8; j++) acc[i][j] = 0.0f;

    for (int k0 = 0; k0 < K; k0 += 16) {
        // Load A tile 128x16, store transposed As[k][m]
#pragma unroll
        for (int l = 0; l < 2; l++) {
            int f = tid + l * 256;       // float4 id, 512 total
            int r = f >> 2;              // row 0..127
            int c4 = f & 3;              // float4 col 0..3
            float4 v = *reinterpret_cast<const float4*>(
                A + (size_t)(m0 + r) * ldA + k0 + c4 * 4);
            As[c4 * 4 + 0][r] = v.x;
            As[c4 * 4 + 1][r] = v.y;
            As[c4 * 4 + 2][r] = v.z;
            As[c4 * 4 + 3][r] = v.w;
        }
        if (TRANSB) {
            // B tile: rows n0..n0+127, cols k0..k0+15 -> Bs[k][n]
#pragma unroll
            for (int l = 0; l < 2; l++) {
                int f = tid + l * 256;
                int r = f >> 2;
                int c4 = f & 3;
                float4 v = *reinterpret_cast<const float4*>(
                    Bp + (size_t)(n0 + r) * ldB + k0 + c4 * 4);
                Bs[c4 * 4 + 0][r] = v.x;
                Bs[c4 * 4 + 1][r] = v.y;
                Bs[c4 * 4 + 2][r] = v.z;
                Bs[c4 * 4 + 3][r] = v.w;
            }
        } else {
            // B tile: rows k0..k0+15, cols n0..n0+127 -> Bs[k][n]
#pragma unroll
            for (int l = 0; l < 2; l++) {
                int f = tid + l * 256;
                int r = f >> 5;          // k row 0..15
                int c4 = f & 31;         // float4 col 0..31
                float4 v = *reinterpret_cast<const float4*>(
                    Bp + (size_t)(k0 + r) * ldB + n0 + c4 * 4);
                *reinterpret_cast<float4*>(&Bs[r][c4 * 4]) = v;
            }
        }
        __syncthreads();

#pragma unroll
        for (int kk = 0; kk < 16; kk++) {
            float a[8], b[8];
#pragma unroll
            for (int i = 0; i < 8; i++) a[i] = As[kk][ty * 8 + i];
#pragma unroll
            for (int j = 0; j < 8; j++) b[j] = Bs[kk][tx * 8 + j];
#pragma unroll
            for (int i = 0; i < 8; i++)
#pragma unroll
                for (int j = 0; j < 8; j++) acc[i][j] = fmaf(a[i], b[j], acc[i][j]);
        }
        __syncthreads();
    }
}

__device__ __forceinline__ void store_tile(float* __restrict__ C, int ldC,
                                           const float acc[8][8]) {
    const int tid = threadIdx.x;
    const int m0 = blockIdx.y * 128 + (tid >> 4) * 8;
    const int n0 = blockIdx.x * 128 + (tid & 15) * 8;
#pragma unroll
    for (int i = 0; i < 8; i++) {
        float4 v0 = make_float4(acc[i][0], acc[i][1], acc[i][2], acc[i][3]);
        float4 v1 = make_float4(acc[i][4], acc[i][5], acc[i][6], acc[i][7]);
        *reinterpret_cast<float4*>(C + (size_t)(m0 + i) * ldC + n0) = v0;
        *reinterpret_cast<float4*>(C + (size_t)(m0 + i) * ldC + n0 + 4) = v1;
    }
}

// ---------------------------------------------------------------------------
// Kernel 1: Q/K/V projections.  C[16384,512] = X[16384,512] * W[512,512]^T
// grid = (512/128, 16384/128, 3); z selects {Wq,Wk,Wv} -> {g_q,g_k,g_v}
// ---------------------------------------------------------------------------
__global__ void __launch_bounds__(256)
qkv_gemm(const float* __restrict__ X, const float* __restrict__ Wq,
         const float* __restrict__ Wk, const float* __restrict__ Wv) {
    const float* W = (blockIdx.z == 0) ? Wq : ((blockIdx.z == 1) ? Wk : Wv);
    float* out = (blockIdx.z == 0) ? g_q : ((blockIdx.z == 1) ? g_k : g_v);
    float acc[8][8];
    gemm_block<true>(X, W, DD, DD, DD, acc);
    store_tile(out, DD, acc);
}

// ---------------------------------------------------------------------------
// Kernel 2: scores = (Q_b * K_b^T) / sqrt(S), masked.  grid = (16,16,8)
// ---------------------------------------------------------------------------
__global__ void __launch_bounds__(256)
scores_gemm(const int* __restrict__ mask) {
    const int b = blockIdx.z;
    const float* Qb = g_q + (size_t)b * SS * DD;
    const float* Kb = g_k + (size_t)b * SS * DD;
    float acc[8][8];
    gemm_block<true>(Qb, Kb, DD, DD, DD, acc);

    float* Scb = g_sc + (size_t)b * SS * SS;
    const int tid = threadIdx.x;
    const int m0 = blockIdx.y * 128 + (tid >> 4) * 8;
    const int n0 = blockIdx.x * 128 + (tid & 15) * 8;
    const float inv_scale = 0.0220970869120796101f;  // 1/sqrt(2048)

    int mk[8];
#pragma unroll
    for (int j = 0; j < 8; j++) mk[j] = mask[b * SS + n0 + j];

#pragma unroll
    for (int i = 0; i < 8; i++) {
        float r[8];
#pragma unroll
        for (int j = 0; j < 8; j++)
            r[j] = mk[j] ? acc[i][j] * inv_scale : -1e30f;
        float4 v0 = make_float4(r[0], r[1], r[2], r[3]);
        float4 v1 = make_float4(r[4], r[5], r[6], r[7]);
        *reinterpret_cast<float4*>(Scb + (size_t)(m0 + i) * SS + n0) = v0;
        *reinterpret_cast<float4*>(Scb + (size_t)(m0 + i) * SS + n0 + 4) = v1;
    }
}

// ---------------------------------------------------------------------------
// Kernel 3: in-place row softmax over g_sc. One block (256 thr) per row.
// ---------------------------------------------------------------------------
__global__ void __launch_bounds__(256)
softmax_kernel() {
    __shared__ float red[8];
    float* p = g_sc + (size_t)blockIdx.x * SS;
    const int tid = threadIdx.x;

    float vals[8];
    float mx = -1e38f;
#pragma unroll
    for (int i = 0; i < 8; i++) {
        vals[i] = p[tid + i * 256];
        mx = fmaxf(mx, vals[i]);
    }
    // block max
#pragma unroll
    for (int o = 16; o > 0; o >>= 1) mx = fmaxf(mx, __shfl_xor_sync(0xffffffffu, mx, o));
    if ((tid & 31) == 0) red[tid >> 5] = mx;
    __syncthreads();
    mx = red[0];
#pragma unroll
    for (int w = 1; w < 8; w++) mx = fmaxf(mx, red[w]);

    float sum = 0.0f;
#pragma unroll
    for (int i = 0; i < 8; i++) {
        vals[i] = __expf(vals[i] - mx);
        sum += vals[i];
    }
#pragma unroll
    for (int o = 16; o > 0; o >>= 1) sum += __shfl_xor_sync(0xffffffffu, sum, o);
    __syncthreads();
    if ((tid & 31) == 0) red[tid >> 5] = sum;
    __syncthreads();
    sum = 0.0f;
#pragma unroll
    for (int w = 0; w < 8; w++) sum += red[w];

    const float r = 1.0f / sum;
#pragma unroll
    for (int i = 0; i < 8; i++) p[tid + i * 256] = vals[i] * r;
}

// ---------------------------------------------------------------------------
// Kernel 4: out_b = P_b[2048,2048] * V_b[2048,512].  grid = (4,16,8)
// ---------------------------------------------------------------------------
__global__ void __launch_bounds__(256)
pv_gemm(float* __restrict__ out) {
    const int b = blockIdx.z;
    const float* Pb = g_sc + (size_t)b * SS * SS;
    const float* Vb = g_v + (size_t)b * SS * DD;
    float acc[8][8];
    gemm_block<false>(Pb, Vb, SS, SS, DD, acc);
    store_tile(out + (size_t)b * SS * DD, DD, acc);
}

// ---------------------------------------------------------------------------
extern "C" void kernel_launch(void* const* d_in, const int* in_sizes, int n_in,
                              void* d_out, int out_size) {
    const float* X    = (const float*)d_in[0];
    const int*   mask = (const int*)  d_in[1];
    const float* Wq   = (const float*)d_in[2];
    const float* Wk   = (const float*)d_in[3];
    const float* Wv   = (const float*)d_in[4];
    float* out = (float*)d_out;

    dim3 blk(256);
    qkv_gemm<<<dim3(DD / 128, (BB * SS) / 128, 3), blk>>>(X, Wq, Wk, Wv);
    scores_gemm<<<dim3(SS / 128, SS / 128, BB), blk>>>(mask);
    softmax_kernel<<<BB * SS, 256>>>();
    pv_gemm<<<dim3(DD / 128, SS / 128, BB), blk>>>(out);
}

// round 3
// speedup vs baseline: 2.4874x; 2.4874x over previous
#include <cuda_runtime.h>
#include <cuda_bf16.h>
#include <cstdint>

#define BB 8
#define SS 2048
#define DD 512

// Scratch (device globals: allocation-free per harness rules)
__device__ __align__(16) float g_q [(size_t)BB * SS * DD];
__device__ __align__(16) float g_k [(size_t)BB * SS * DD];
__device__ __align__(16) float g_vt[(size_t)BB * DD * SS];   // V transposed: [b][d][s]
__device__ __align__(16) float g_sc[(size_t)BB * SS * SS];

static __device__ __forceinline__ uint32_t su32(const void* p) {
    return (uint32_t)__cvta_generic_to_shared(p);
}

__device__ __forceinline__ void ldm_x4(uint32_t addr, uint32_t r[4]) {
    asm volatile("ldmatrix.sync.aligned.m8n8.x4.shared.b16 {%0,%1,%2,%3}, [%4];"
                 : "=r"(r[0]), "=r"(r[1]), "=r"(r[2]), "=r"(r[3]) : "r"(addr));
}
__device__ __forceinline__ void mma_bf16(float c[4], const uint32_t a[4], const uint32_t b[2]) {
    asm volatile(
        "mma.sync.aligned.m16n8k16.row.col.f32.bf16.bf16.f32 "
        "{%0,%1,%2,%3}, {%4,%5,%6,%7}, {%8,%9}, {%0,%1,%2,%3};"
        : "+f"(c[0]), "+f"(c[1]), "+f"(c[2]), "+f"(c[3])
        : "r"(a[0]), "r"(a[1]), "r"(a[2]), "r"(a[3]), "r"(b[0]), "r"(b[1]));
}

// ---------------------------------------------------------------------------
// Block GEMM 128x128 tile: C = A * B^T via bf16 split (Ah*Bh + Ah*Bl + Al*Bh)
// A: row-major [M,K] ldA; B: row-major [N,K] ldB. K % 32 == 0.
// 256 threads = 8 warps in 4(m) x 2(n); warp tile 32x64.
// acc[mi][nj][4]: mma m16n8 fragments.
// ---------------------------------------------------------------------------
__device__ __forceinline__ void gemm_tile(const float* __restrict__ A,
                                          const float* __restrict__ B,
                                          int K, int ldA, int ldB,
                                          float acc[2][8][4]) {
    __shared__ __align__(16) __nv_bfloat16 Ah[128][40];
    __shared__ __align__(16) __nv_bfloat16 Al[128][40];
    __shared__ __align__(16) __nv_bfloat16 Bh[128][40];
    __shared__ __align__(16) __nv_bfloat16 Bl[128][40];

    const int tid  = threadIdx.x;
    const int lane = tid & 31;
    const int w    = tid >> 5;
    const int wm   = w & 3;        // 0..3
    const int wn   = w >> 2;       // 0..1
    const int m0   = blockIdx.y * 128;
    const int n0   = blockIdx.x * 128;

#pragma unroll
    for (int mi = 0; mi < 2; mi++)
#pragma unroll
        for (int nj = 0; nj < 8; nj++)
#pragma unroll
            for (int e = 0; e < 4; e++) acc[mi][nj][e] = 0.0f;

    for (int k0 = 0; k0 < K; k0 += 32) {
        // ---- load + split A tile (128x32) ----
#pragma unroll
        for (int l = 0; l < 4; l++) {
            int f = tid + l * 256;           // 1024 float4s
            int r = f >> 3;                  // row 0..127
            int c = f & 7;                   // float4 col 0..7
            float4 v = *reinterpret_cast<const float4*>(
                A + (size_t)(m0 + r) * ldA + k0 + c * 4);
            union { __nv_bfloat16 b[4]; uint2 u; } th, tl;
            const float* pe = &v.x;
#pragma unroll
            for (int e = 0; e < 4; e++) {
                __nv_bfloat16 hb = __float2bfloat16(pe[e]);
                th.b[e] = hb;
                tl.b[e] = __float2bfloat16(pe[e] - __bfloat162float(hb));
            }
            *reinterpret_cast<uint2*>(&Ah[r][c * 4]) = th.u;
            *reinterpret_cast<uint2*>(&Al[r][c * 4]) = tl.u;
        }
        // ---- load + split B tile (128x32) ----
#pragma unroll
        for (int l = 0; l < 4; l++) {
            int f = tid + l * 256;
            int r = f >> 3;
            int c = f & 7;
            float4 v = *reinterpret_cast<const float4*>(
                B + (size_t)(n0 + r) * ldB + k0 + c * 4);
            union { __nv_bfloat16 b[4]; uint2 u; } th, tl;
            const float* pe = &v.x;
#pragma unroll
            for (int e = 0; e < 4; e++) {
                __nv_bfloat16 hb = __float2bfloat16(pe[e]);
                th.b[e] = hb;
                tl.b[e] = __float2bfloat16(pe[e] - __bfloat162float(hb));
            }
            *reinterpret_cast<uint2*>(&Bh[r][c * 4]) = th.u;
            *reinterpret_cast<uint2*>(&Bl[r][c * 4]) = tl.u;
        }
        __syncthreads();

#pragma unroll
        for (int kk = 0; kk < 32; kk += 16) {
            uint32_t ah[2][4], al[2][4];
#pragma unroll
            for (int mi = 0; mi < 2; mi++) {
                int row = wm * 32 + mi * 16 + (lane & 15);
                int col = kk + (lane >> 4) * 8;
                ldm_x4(su32(&Ah[row][col]), ah[mi]);
                ldm_x4(su32(&Al[row][col]), al[mi]);
            }
            uint32_t bh[8][2], bl[8][2];
#pragma unroll
            for (int nj4 = 0; nj4 < 4; nj4++) {
                int row = wn * 64 + nj4 * 16 + (lane & 7) + ((lane >> 4) << 3);
                int col = kk + (((lane >> 3) & 1) << 3);
                uint32_t t[4];
                ldm_x4(su32(&Bh[row][col]), t);
                bh[2 * nj4][0] = t[0]; bh[2 * nj4][1] = t[1];
                bh[2 * nj4 + 1][0] = t[2]; bh[2 * nj4 + 1][1] = t[3];
                ldm_x4(su32(&Bl[row][col]), t);
                bl[2 * nj4][0] = t[0]; bl[2 * nj4][1] = t[1];
                bl[2 * nj4 + 1][0] = t[2]; bl[2 * nj4 + 1][1] = t[3];
            }
#pragma unroll
            for (int mi = 0; mi < 2; mi++)
#pragma unroll
                for (int nj = 0; nj < 8; nj++) {
                    mma_bf16(acc[mi][nj], ah[mi], bh[nj]);
                    mma_bf16(acc[mi][nj], ah[mi], bl[nj]);
                    mma_bf16(acc[mi][nj], al[mi], bh[nj]);
                }
        }
        __syncthreads();
    }
}

// Standard epilogue: C[m][n] (row-major, ldC), optional scale.
__device__ __forceinline__ void store_acc(float* __restrict__ C, int ldC,
                                          const float acc[2][8][4]) {
    const int lane = threadIdx.x & 31;
    const int w = threadIdx.x >> 5;
    const int wm = w & 3, wn = w >> 2;
    const int mb = blockIdx.y * 128 + wm * 32 + (lane >> 2);
    const int nb = blockIdx.x * 128 + wn * 64 + (lane & 3) * 2;
#pragma unroll
    for (int mi = 0; mi < 2; mi++) {
        int m = mb + mi * 16;
#pragma unroll
        for (int nj = 0; nj < 8; nj++) {
            int n = nb + nj * 8;
            *reinterpret_cast<float2*>(C + (size_t)m * ldC + n) =
                make_float2(acc[mi][nj][0], acc[mi][nj][1]);
            *reinterpret_cast<float2*>(C + (size_t)(m + 8) * ldC + n) =
                make_float2(acc[mi][nj][2], acc[mi][nj][3]);
        }
    }
}

// ---------------------------------------------------------------------------
// Kernel 1: QKV. grid=(4, 128, 3); z: 0=Q, 1=K, 2=V(transposed store)
// ---------------------------------------------------------------------------
__global__ void __launch_bounds__(256)
qkv_mm(const float* __restrict__ X, const float* __restrict__ Wq,
       const float* __restrict__ Wk, const float* __restrict__ Wv) {
    const float* W = (blockIdx.z == 0) ? Wq : ((blockIdx.z == 1) ? Wk : Wv);
    float acc[2][8][4];
    gemm_tile(X, W, DD, DD, DD, acc);

    if (blockIdx.z < 2) {
        store_acc((blockIdx.z == 0) ? g_q : g_k, DD, acc);
    } else {
        const int lane = threadIdx.x & 31;
        const int w = threadIdx.x >> 5;
        const int wm = w & 3, wn = w >> 2;
        const int mb = blockIdx.y * 128 + wm * 32 + (lane >> 2);
        const int nb = blockIdx.x * 128 + wn * 64 + (lane & 3) * 2;
        const int b = mb >> 11;
        float* vb = g_vt + (size_t)b * DD * SS;
#pragma unroll
        for (int mi = 0; mi < 2; mi++) {
            int s = (mb & 2047) + mi * 16;
#pragma unroll
            for (int nj = 0; nj < 8; nj++) {
                int d = nb + nj * 8;
                vb[(size_t)d * SS + s]           = acc[mi][nj][0];
                vb[(size_t)(d + 1) * SS + s]     = acc[mi][nj][1];
                vb[(size_t)d * SS + s + 8]       = acc[mi][nj][2];
                vb[(size_t)(d + 1) * SS + s + 8] = acc[mi][nj][3];
            }
        }
    }
}

// ---------------------------------------------------------------------------
// Kernel 2: scores = (Q K^T)/sqrt(S), masked. grid=(16,16,8)
// ---------------------------------------------------------------------------
__global__ void __launch_bounds__(256)
scores_mm(const int* __restrict__ mask) {
    const int b = blockIdx.z;
    float acc[2][8][4];
    gemm_tile(g_q + (size_t)b * SS * DD, g_k + (size_t)b * SS * DD,
              DD, DD, DD, acc);

    const int lane = threadIdx.x & 31;
    const int w = threadIdx.x >> 5;
    const int wm = w & 3, wn = w >> 2;
    const int mb = blockIdx.y * 128 + wm * 32 + (lane >> 2);
    const int nb = blockIdx.x * 128 + wn * 64 + (lane & 3) * 2;
    const float inv_scale = 0.0220970869120796101f;  // 1/sqrt(2048)
    float* Scb = g_sc + (size_t)b * SS * SS;
    const int* mrow = mask + b * SS;

#pragma unroll
    for (int nj = 0; nj < 8; nj++) {
        int n = nb + nj * 8;
        float f0 = mrow[n]     ? inv_scale : 0.0f;
        float g0 = mrow[n]     ? 0.0f      : -1e30f;
        float f1 = mrow[n + 1] ? inv_scale : 0.0f;
        float g1 = mrow[n + 1] ? 0.0f      : -1e30f;
#pragma unroll
        for (int mi = 0; mi < 2; mi++) {
            int m = mb + mi * 16;
            *reinterpret_cast<float2*>(Scb + (size_t)m * SS + n) =
                make_float2(acc[mi][nj][0] * f0 + g0, acc[mi][nj][1] * f1 + g1);
            *reinterpret_cast<float2*>(Scb + (size_t)(m + 8) * SS + n) =
                make_float2(acc[mi][nj][2] * f0 + g0, acc[mi][nj][3] * f1 + g1);
        }
    }
}

// ---------------------------------------------------------------------------
// Kernel 3: in-place row softmax. One block (256 thr) per row.
// ---------------------------------------------------------------------------
__global__ void __launch_bounds__(256)
softmax_kernel() {
    __shared__ float red[8];
    float* p = g_sc + (size_t)blockIdx.x * SS;
    const int tid = threadIdx.x;

    float vals[8];
    float mx = -1e38f;
#pragma unroll
    for (int i = 0; i < 8; i++) {
        vals[i] = p[tid + i * 256];
        mx = fmaxf(mx, vals[i]);
    }
#pragma unroll
    for (int o = 16; o > 0; o >>= 1) mx = fmaxf(mx, __shfl_xor_sync(0xffffffffu, mx, o));
    if ((tid & 31) == 0) red[tid >> 5] = mx;
    __syncthreads();
    mx = red[0];
#pragma unroll
    for (int wi = 1; wi < 8; wi++) mx = fmaxf(mx, red[wi]);

    float sum = 0.0f;
#pragma unroll
    for (int i = 0; i < 8; i++) {
        vals[i] = __expf(vals[i] - mx);
        sum += vals[i];
    }
#pragma unroll
    for (int o = 16; o > 0; o >>= 1) sum += __shfl_xor_sync(0xffffffffu, sum, o);
    __syncthreads();
    if ((tid & 31) == 0) red[tid >> 5] = sum;
    __syncthreads();
    sum = 0.0f;
#pragma unroll
    for (int wi = 0; wi < 8; wi++) sum += red[wi];

    const float r = 1.0f / sum;
#pragma unroll
    for (int i = 0; i < 8; i++) p[tid + i * 256] = vals[i] * r;
}

// ---------------------------------------------------------------------------
// Kernel 4: out_b = P_b * V_b  (V^T is [d][s], K-major). grid=(4,16,8)
// ---------------------------------------------------------------------------
__global__ void __launch_bounds__(256)
pv_mm(float* __restrict__ out) {
    const int b = blockIdx.z;
    float acc[2][8][4];
    gemm_tile(g_sc + (size_t)b * SS * SS, g_vt + (size_t)b * DD * SS,
              SS, SS, SS, acc);
    store_acc(out + (size_t)b * SS * DD, DD, acc);
}

// ---------------------------------------------------------------------------
extern "C" void kernel_launch(void* const* d_in, const int* in_sizes, int n_in,
                              void* d_out, int out_size) {
    const float* X    = (const float*)d_in[0];
    const int*   mask = (const int*)  d_in[1];
    const float* Wq   = (const float*)d_in[2];
    const float* Wk   = (const float*)d_in[3];
    const float* Wv   = (const float*)d_in[4];
    float* out = (float*)d_out;

    dim3 blk(256);
    qkv_mm<<<dim3(DD / 128, (BB * SS) / 128, 3), blk>>>(X, Wq, Wk, Wv);
    scores_mm<<<dim3(SS / 128, SS / 128, BB), blk>>>(mask);
    softmax_kernel<<<BB * SS, 256>>>();
    pv_mm<<<dim3(DD / 128, SS / 128, BB), blk>>>(out);
}

// round 4
// speedup vs baseline: 2.7268x; 1.0963x over previous
#include <cuda_runtime.h>
#include <cuda_bf16.h>
#include <cstdint>

#define BB 8
#define SS 2048
#define DD 512

// ---------------- device-global scratch (allocation-free) -------------------
__device__ __align__(16) __nv_bfloat16 g_xh[(size_t)BB * SS * DD];
__device__ __align__(16) __nv_bfloat16 g_xl[(size_t)BB * SS * DD];
__device__ __align__(16) __nv_bfloat16 g_wh[3 * DD * DD];
__device__ __align__(16) __nv_bfloat16 g_wl[3 * DD * DD];
__device__ __align__(16) __nv_bfloat16 g_qh[(size_t)BB * SS * DD];
__device__ __align__(16) __nv_bfloat16 g_ql[(size_t)BB * SS * DD];
__device__ __align__(16) __nv_bfloat16 g_kh[(size_t)BB * SS * DD];
__device__ __align__(16) __nv_bfloat16 g_kl[(size_t)BB * SS * DD];
__device__ __align__(16) __nv_bfloat16 g_vth[(size_t)BB * DD * SS];  // [b][d][s]
__device__ __align__(16) __nv_bfloat16 g_vtl[(size_t)BB * DD * SS];
__device__ __align__(16) float         g_sc [(size_t)BB * SS * SS];
__device__ __align__(16) __nv_bfloat16 g_ph[(size_t)BB * SS * SS];
__device__ __align__(16) __nv_bfloat16 g_pl[(size_t)BB * SS * SS];

// ---------------- PTX helpers ----------------------------------------------
static __device__ __forceinline__ uint32_t su32(const void* p) {
    return (uint32_t)__cvta_generic_to_shared(p);
}
__device__ __forceinline__ void cp16(uint32_t dst, const void* src) {
    asm volatile("cp.async.ca.shared.global [%0], [%1], 16;" :: "r"(dst), "l"(src));
}
__device__ __forceinline__ void cp_commit() {
    asm volatile("cp.async.commit_group;" ::: "memory");
}
template <int N>
__device__ __forceinline__ void cp_wait() {
    asm volatile("cp.async.wait_group %0;" :: "n"(N) : "memory");
}
__device__ __forceinline__ void ldm_x4(uint32_t addr, uint32_t r[4]) {
    asm volatile("ldmatrix.sync.aligned.m8n8.x4.shared.b16 {%0,%1,%2,%3}, [%4];"
                 : "=r"(r[0]), "=r"(r[1]), "=r"(r[2]), "=r"(r[3]) : "r"(addr));
}
__device__ __forceinline__ void mma_bf16(float c[4], const uint32_t a[4], const uint32_t b[2]) {
    asm volatile(
        "mma.sync.aligned.m16n8k16.row.col.f32.bf16.bf16.f32 "
        "{%0,%1,%2,%3}, {%4,%5,%6,%7}, {%8,%9}, {%0,%1,%2,%3};"
        : "+f"(c[0]), "+f"(c[1]), "+f"(c[2]), "+f"(c[3])
        : "r"(a[0]), "r"(a[1]), "r"(a[2]), "r"(a[3]), "r"(b[0]), "r"(b[1]));
}
__device__ __forceinline__ uint32_t pack_split(float a, float b) {
    __nv_bfloat162 t(__float2bfloat16(a), __float2bfloat16(b));
    return *reinterpret_cast<uint32_t*>(&t);
}

// ---------------- pipelined block GEMM --------------------------------------
// C(128x128) += (Ah+Al)*(Bh+Bl)^T, 3-pass bf16. A:[M,K] ldA, B:[N,K] ldB (K-major).
// smem: 2 stages x { Ah, Al, Bh, Bl } tiles of 128x32 bf16, row pitch 80B.
#define TPB 10240   // tile bytes (128 * 80)
#define STG 40960   // stage bytes

__device__ __forceinline__ void gemm_pipe(const __nv_bfloat16* __restrict__ Agh,
                                          const __nv_bfloat16* __restrict__ Agl,
                                          const __nv_bfloat16* __restrict__ Bgh,
                                          const __nv_bfloat16* __restrict__ Bgl,
                                          int K, int ldA, int ldB,
                                          char* smem, float acc[2][8][4]) {
    const int tid  = threadIdx.x;
    const int lane = tid & 31;
    const int w    = tid >> 5;
    const int wm   = w & 3;
    const int wn   = w >> 2;
    const int m0   = blockIdx.y * 128;
    const int n0   = blockIdx.x * 128;
    const uint32_t sbase = su32(smem);

#pragma unroll
    for (int mi = 0; mi < 2; mi++)
#pragma unroll
        for (int nj = 0; nj < 8; nj++)
#pragma unroll
            for (int e = 0; e < 4; e++) acc[mi][nj][e] = 0.0f;

    const int NK = K >> 5;

    // per-thread load coords: two 16B chunks per tile
    const int r0 = tid >> 2, c0 = tid & 3;          // chunk tid
    const int r1 = (tid + 256) >> 2, c1 = (tid + 256) & 3;

#define ISSUE(kidx, buf)                                                          \
    do {                                                                          \
        const int k0 = (kidx) << 5;                                               \
        uint32_t st = sbase + (buf) * STG;                                        \
        {                                                                         \
            size_t ga = (size_t)(m0 + r0) * ldA + k0 + c0 * 8;                    \
            size_t gb = (size_t)(n0 + r0) * ldB + k0 + c0 * 8;                    \
            uint32_t da = st + r0 * 80 + c0 * 16;                                 \
            cp16(da,            Agh + ga);                                        \
            cp16(da + TPB,      Agl + ga);                                        \
            cp16(da + 2 * TPB,  Bgh + gb);                                        \
            cp16(da + 3 * TPB,  Bgl + gb);                                        \
        }                                                                         \
        {                                                                         \
            size_t ga = (size_t)(m0 + r1) * ldA + k0 + c1 * 8;                    \
            size_t gb = (size_t)(n0 + r1) * ldB + k0 + c1 * 8;                    \
            uint32_t da = st + r1 * 80 + c1 * 16;                                 \
            cp16(da,            Agh + ga);                                        \
            cp16(da + TPB,      Agl + ga);                                        \
            cp16(da + 2 * TPB,  Bgh + gb);                                        \
            cp16(da + 3 * TPB,  Bgl + gb);                                        \
        }                                                                         \
        cp_commit();                                                              \
    } while (0)

    ISSUE(0, 0);

    for (int k = 0; k < NK; k++) {
        const int buf = k & 1;
        if (k + 1 < NK) { ISSUE(k + 1, buf ^ 1); cp_wait<1>(); }
        else            { cp_wait<0>(); }
        __syncthreads();

        const uint32_t sAh = sbase + buf * STG;
        const uint32_t sAl = sAh + TPB;
        const uint32_t sBh = sAh + 2 * TPB;
        const uint32_t sBl = sAh + 3 * TPB;

#pragma unroll
        for (int kk = 0; kk < 32; kk += 16) {
            uint32_t ah[2][4], al[2][4];
#pragma unroll
            for (int mi = 0; mi < 2; mi++) {
                uint32_t off = (uint32_t)(wm * 32 + mi * 16 + (lane & 15)) * 80
                             + (kk + (lane >> 4) * 8) * 2;
                ldm_x4(sAh + off, ah[mi]);
                ldm_x4(sAl + off, al[mi]);
            }
            uint32_t bh[8][2], bl[8][2];
#pragma unroll
            for (int nj4 = 0; nj4 < 4; nj4++) {
                uint32_t off = (uint32_t)(wn * 64 + nj4 * 16 + (lane & 7) + ((lane >> 4) << 3)) * 80
                             + (kk + (((lane >> 3) & 1) << 3)) * 2;
                uint32_t t[4];
                ldm_x4(sBh + off, t);
                bh[2 * nj4][0] = t[0]; bh[2 * nj4][1] = t[1];
                bh[2 * nj4 + 1][0] = t[2]; bh[2 * nj4 + 1][1] = t[3];
                ldm_x4(sBl + off, t);
                bl[2 * nj4][0] = t[0]; bl[2 * nj4][1] = t[1];
                bl[2 * nj4 + 1][0] = t[2]; bl[2 * nj4 + 1][1] = t[3];
            }
#pragma unroll
            for (int mi = 0; mi < 2; mi++)
#pragma unroll
                for (int nj = 0; nj < 8; nj++) {
                    mma_bf16(acc[mi][nj], ah[mi], bh[nj]);
                    mma_bf16(acc[mi][nj], ah[mi], bl[nj]);
                    mma_bf16(acc[mi][nj], al[mi], bh[nj]);
                }
        }
        __syncthreads();
    }
#undef ISSUE
}

// ---------------- epilogues --------------------------------------------------
__device__ __forceinline__ void store_acc_f32(float* __restrict__ C, int ldC,
                                              const float acc[2][8][4]) {
    const int lane = threadIdx.x & 31;
    const int w = threadIdx.x >> 5;
    const int wm = w & 3, wn = w >> 2;
    const int mb = blockIdx.y * 128 + wm * 32 + (lane >> 2);
    const int nb = blockIdx.x * 128 + wn * 64 + (lane & 3) * 2;
#pragma unroll
    for (int mi = 0; mi < 2; mi++) {
        int m = mb + mi * 16;
#pragma unroll
        for (int nj = 0; nj < 8; nj++) {
            int n = nb + nj * 8;
            *reinterpret_cast<float2*>(C + (size_t)m * ldC + n) =
                make_float2(acc[mi][nj][0], acc[mi][nj][1]);
            *reinterpret_cast<float2*>(C + (size_t)(m + 8) * ldC + n) =
                make_float2(acc[mi][nj][2], acc[mi][nj][3]);
        }
    }
}

__device__ __forceinline__ void store_acc_split(__nv_bfloat16* __restrict__ H,
                                                __nv_bfloat16* __restrict__ L,
                                                int ldC, const float acc[2][8][4]) {
    const int lane = threadIdx.x & 31;
    const int w = threadIdx.x >> 5;
    const int wm = w & 3, wn = w >> 2;
    const int mb = blockIdx.y * 128 + wm * 32 + (lane >> 2);
    const int nb = blockIdx.x * 128 + wn * 64 + (lane & 3) * 2;
#pragma unroll
    for (int mi = 0; mi < 2; mi++) {
        int m = mb + mi * 16;
#pragma unroll
        for (int nj = 0; nj < 8; nj++) {
            int n = nb + nj * 8;
#pragma unroll
            for (int half = 0; half < 2; half++) {
                float a = acc[mi][nj][half * 2], b = acc[mi][nj][half * 2 + 1];
                float ha = __bfloat162float(__float2bfloat16(a));
                float hb = __bfloat162float(__float2bfloat16(b));
                size_t idx = (size_t)(m + half * 8) * ldC + n;
                *reinterpret_cast<uint32_t*>(H + idx) = pack_split(a, b);
                *reinterpret_cast<uint32_t*>(L + idx) = pack_split(a - ha, b - hb);
            }
        }
    }
}

// ---------------- kernels ----------------------------------------------------
__global__ void __launch_bounds__(256)
split_kernel(const float* __restrict__ src, __nv_bfloat16* __restrict__ h,
             __nv_bfloat16* __restrict__ l, int n4) {
    int i = blockIdx.x * blockDim.x + threadIdx.x;
    if (i >= n4) return;
    float4 v = reinterpret_cast<const float4*>(src)[i];
    float hx = __bfloat162float(__float2bfloat16(v.x));
    float hy = __bfloat162float(__float2bfloat16(v.y));
    float hz = __bfloat162float(__float2bfloat16(v.z));
    float hw = __bfloat162float(__float2bfloat16(v.w));
    uint2 hv = make_uint2(pack_split(v.x, v.y), pack_split(v.z, v.w));
    uint2 lv = make_uint2(pack_split(v.x - hx, v.y - hy), pack_split(v.z - hz, v.w - hw));
    reinterpret_cast<uint2*>(h)[i] = hv;
    reinterpret_cast<uint2*>(l)[i] = lv;
}

// QKV: grid=(4, 128, 3). z: 0=Q, 1=K, 2=V(transposed split store)
__global__ void __launch_bounds__(256, 2)
qkv_mm(int dummy) {
    extern __shared__ char smem[];
    const int z = blockIdx.z;
    float acc[2][8][4];
    gemm_pipe(g_xh, g_xl, g_wh + z * DD * DD, g_wl + z * DD * DD,
              DD, DD, DD, smem, acc);

    if (z == 0)      store_acc_split(g_qh, g_ql, DD, acc);
    else if (z == 1) store_acc_split(g_kh, g_kl, DD, acc);
    else {
        const int lane = threadIdx.x & 31;
        const int w = threadIdx.x >> 5;
        const int wm = w & 3, wn = w >> 2;
        const int mb = blockIdx.y * 128 + wm * 32 + (lane >> 2);
        const int nb = blockIdx.x * 128 + wn * 64 + (lane & 3) * 2;
        const int b = mb >> 11;
        __nv_bfloat16* vh = g_vth + (size_t)b * DD * SS;
        __nv_bfloat16* vl = g_vtl + (size_t)b * DD * SS;
#pragma unroll
        for (int mi = 0; mi < 2; mi++) {
            int s = (mb & 2047) + mi * 16;
#pragma unroll
            for (int nj = 0; nj < 8; nj++) {
                int d = nb + nj * 8;
#pragma unroll
                for (int e = 0; e < 4; e++) {
                    float v = acc[mi][nj][e];
                    float hv = __bfloat162float(__float2bfloat16(v));
                    size_t idx = (size_t)(d + (e & 1)) * SS + s + (e >> 1) * 8;
                    vh[idx] = __float2bfloat16(v);
                    vl[idx] = __float2bfloat16(v - hv);
                }
            }
        }
    }
}

// scores: grid=(16,16,8)
__global__ void __launch_bounds__(256, 2)
scores_mm(const int* __restrict__ mask) {
    extern __shared__ char smem[];
    const int b = blockIdx.z;
    float acc[2][8][4];
    gemm_pipe(g_qh + (size_t)b * SS * DD, g_ql + (size_t)b * SS * DD,
              g_kh + (size_t)b * SS * DD, g_kl + (size_t)b * SS * DD,
              DD, DD, DD, smem, acc);

    const int lane = threadIdx.x & 31;
    const int w = threadIdx.x >> 5;
    const int wm = w & 3, wn = w >> 2;
    const int mb = blockIdx.y * 128 + wm * 32 + (lane >> 2);
    const int nb = blockIdx.x * 128 + wn * 64 + (lane & 3) * 2;
    const float inv_scale = 0.0220970869120796101f;  // 1/sqrt(2048)
    float* Scb = g_sc + (size_t)b * SS * SS;
    const int* mrow = mask + b * SS;

#pragma unroll
    for (int nj = 0; nj < 8; nj++) {
        int n = nb + nj * 8;
        float f0 = mrow[n]     ? inv_scale : 0.0f;
        float g0 = mrow[n]     ? 0.0f      : -1e30f;
        float f1 = mrow[n + 1] ? inv_scale : 0.0f;
        float g1 = mrow[n + 1] ? 0.0f      : -1e30f;
#pragma unroll
        for (int mi = 0; mi < 2; mi++) {
            int m = mb + mi * 16;
            *reinterpret_cast<float2*>(Scb + (size_t)m * SS + n) =
                make_float2(acc[mi][nj][0] * f0 + g0, acc[mi][nj][1] * f1 + g1);
            *reinterpret_cast<float2*>(Scb + (size_t)(m + 8) * SS + n) =
                make_float2(acc[mi][nj][2] * f0 + g0, acc[mi][nj][3] * f1 + g1);
        }
    }
}

// softmax: one block per row; writes split bf16 probs
__global__ void __launch_bounds__(256)
softmax_kernel() {
    __shared__ float red[8];
    const size_t base = (size_t)blockIdx.x * SS;
    float* p = g_sc + base;
    const int tid = threadIdx.x;

    float vals[8];
    float mx = -1e38f;
#pragma unroll
    for (int i = 0; i < 8; i++) {
        vals[i] = p[tid + i * 256];
        mx = fmaxf(mx, vals[i]);
    }
#pragma unroll
    for (int o = 16; o > 0; o >>= 1) mx = fmaxf(mx, __shfl_xor_sync(0xffffffffu, mx, o));
    if ((tid & 31) == 0) red[tid >> 5] = mx;
    __syncthreads();
    mx = red[0];
#pragma unroll
    for (int wi = 1; wi < 8; wi++) mx = fmaxf(mx, red[wi]);

    float sum = 0.0f;
#pragma unroll
    for (int i = 0; i < 8; i++) {
        vals[i] = __expf(vals[i] - mx);
        sum += vals[i];
    }
#pragma unroll
    for (int o = 16; o > 0; o >>= 1) sum += __shfl_xor_sync(0xffffffffu, sum, o);
    __syncthreads();
    if ((tid & 31) == 0) red[tid >> 5] = sum;
    __syncthreads();
    sum = 0.0f;
#pragma unroll
    for (int wi = 0; wi < 8; wi++) sum += red[wi];

    const float r = 1.0f / sum;
#pragma unroll
    for (int i = 0; i < 8; i++) {
        float v = vals[i] * r;
        float hv = __bfloat162float(__float2bfloat16(v));
        g_ph[base + tid + i * 256] = __float2bfloat16(v);
        g_pl[base + tid + i * 256] = __float2bfloat16(v - hv);
    }
}

// PV: grid=(4,16,8)
__global__ void __launch_bounds__(256, 2)
pv_mm(float* __restrict__ out) {
    extern __shared__ char smem[];
    const int b = blockIdx.z;
    float acc[2][8][4];
    gemm_pipe(g_ph + (size_t)b * SS * SS, g_pl + (size_t)b * SS * SS,
              g_vth + (size_t)b * DD * SS, g_vtl + (size_t)b * DD * SS,
              SS, SS, SS, smem, acc);
    store_acc_f32(out + (size_t)b * SS * DD, DD, acc);
}

// ---------------------------------------------------------------------------
extern "C" void kernel_launch(void* const* d_in, const int* in_sizes, int n_in,
                              void* d_out, int out_size) {
    const float* X    = (const float*)d_in[0];
    const int*   mask = (const int*)  d_in[1];
    const float* Wq   = (const float*)d_in[2];
    const float* Wk   = (const float*)d_in[3];
    const float* Wv   = (const float*)d_in[4];
    float* out = (float*)d_out;

    static bool attr_done = false;
    if (!attr_done) {
        cudaFuncSetAttribute(qkv_mm,    cudaFuncAttributeMaxDynamicSharedMemorySize, 2 * STG);
        cudaFuncSetAttribute(scores_mm, cudaFuncAttributeMaxDynamicSharedMemorySize, 2 * STG);
        cudaFuncSetAttribute(pv_mm,     cudaFuncAttributeMaxDynamicSharedMemorySize, 2 * STG);
        attr_done = true;
    }

    __nv_bfloat16 *xh, *xl, *wh, *wl;
    cudaGetSymbolAddress((void**)&xh, g_xh);
    cudaGetSymbolAddress((void**)&xl, g_xl);
    cudaGetSymbolAddress((void**)&wh, g_wh);
    cudaGetSymbolAddress((void**)&wl, g_wl);

    const int nX4 = (BB * SS * DD) / 4;
    const int nW4 = (DD * DD) / 4;
    split_kernel<<<(nX4 + 255) / 256, 256>>>(X, xh, xl, nX4);
    split_kernel<<<(nW4 + 255) / 256, 256>>>(Wq, wh,            wl,            nW4);
    split_kernel<<<(nW4 + 255) / 256, 256>>>(Wk, wh + DD * DD,  wl + DD * DD,  nW4);
    split_kernel<<<(nW4 + 255) / 256, 256>>>(Wv, wh + 2*DD*DD,  wl + 2*DD*DD,  nW4);

    dim3 blk(256);
    qkv_mm<<<dim3(DD / 128, (BB * SS) / 128, 3), blk, 2 * STG>>>(0);
    scores_mm<<<dim3(SS / 128, SS / 128, BB), blk, 2 * STG>>>(mask);
    softmax_kernel<<<BB * SS, 256>>>();
    pv_mm<<<dim3(DD / 128, SS / 128, BB), blk, 2 * STG>>>(out);
}